// round 9
// baseline (speedup 1.0000x reference)
#include <cuda_runtime.h>
#include <cuda_fp16.h>

// AntiAliasInterpolation2d: depthwise 13x13 Gaussian, stride 4, zero pad 6.
// Input [32,3,512,512] f32, weight [3,1,13,13] f32, output [32,3,128,128] f32.
//
// Separable (exact): 2D kernel = outer(g,g), g[j] = k2[6][j]/sqrt(k2[6][6]),
// g symmetric, sum(g) == 1.
// R9: two streaming kernels, FP16 intermediate (12.6 MB).
//   K1 (hpass): lane = ONE output, 4 UNIT-STRIDE float4 loads (4 lines per
//       warp instruction — R8's pair mapping doubled lines/wavefront), fp16 store.
//   K2 (vpass): thread = one output float4, 13 independent 8B loads (unchanged).

#define IW   512
#define IW4  128                 // input row in float4
#define OW   128

__device__ __half g_tmp[96 * 512 * 128];   // 12.6 MB scratch

__device__ __forceinline__ float hfilt(const float4* __restrict__ row,
                                       int ox, const float* __restrict__ g)
{
    const float4 z4 = make_float4(0.f, 0.f, 0.f, 0.f);
    // taps x = 4*ox-6 .. 4*ox+6 live in float4 blocks ox-2 .. ox+1
    float4 a0 = (ox >= 2)       ? row[ox - 2] : z4;   // taps 0,1 (z,w)
    float4 a1 = (ox >= 1)       ? row[ox - 1] : z4;   // taps 2..5
    float4 a2 =                   row[ox];            // taps 6..9
    float4 a3 = (ox <= IW4 - 2) ? row[ox + 1] : z4;   // taps 10..12 (x,y,z)

    // two independent chains: dependent depth ~7 instead of 13
    float e0 =       g[0] * a0.z;
    float e1 =       g[1] * a0.w;
    e0 = fmaf(g[2], a1.x, e0);
    e1 = fmaf(g[3], a1.y, e1);
    e0 = fmaf(g[4], a1.z, e0);
    e1 = fmaf(g[5], a1.w, e1);
    e0 = fmaf(g[6], a2.x, e0);
    e1 = fmaf(g[5], a2.y, e1);   // k7
    e0 = fmaf(g[4], a2.z, e0);   // k8
    e1 = fmaf(g[3], a2.w, e1);   // k9
    e0 = fmaf(g[2], a3.x, e0);   // k10
    e1 = fmaf(g[1], a3.y, e1);   // k11
    e0 = fmaf(g[0], a3.z, e0);   // k12
    return e0 + e1;
}

// K1: warp = one input row (49152 rows), 8 rows per CTA.
__global__ __launch_bounds__(256, 7)
void hpass_kernel(const float* __restrict__ inp, const float* __restrict__ w)
{
    __shared__ float sw[8];
    const int tid  = threadIdx.x;
    const int lane = tid & 31;
    const int wid  = tid >> 5;

    const int row0 = blockIdx.x * 8;          // 8 | 512 -> CTA within one image
    const int c    = (row0 >> 9) % 3;
    if (tid < 7)
        sw[tid] = w[c * 169 + 78 + tid] / sqrtf(w[c * 169 + 84]);
    __syncthreads();

    float g[7];
#pragma unroll
    for (int k = 0; k < 7; k++) g[k] = sw[k];

    const int row = row0 + wid;               // nc*512 + iy
    const float4* r4 = reinterpret_cast<const float4*>(inp) + (size_t)row * IW4;
    __half* dst = g_tmp + (size_t)row * OW;

#pragma unroll
    for (int j = 0; j < 4; j++) {
        const int ox = lane + 32 * j;         // unit inter-lane stride (16 B)
        dst[ox] = __float2half_rn(hfilt(r4, ox, g));
    }
}

// K2: thread = one output float4 (393216 of them), 8 output rows per CTA.
__global__ __launch_bounds__(256, 6)
void vpass_kernel(const float* __restrict__ w, float* __restrict__ out)
{
    __shared__ float sw[8];
    const int tid = threadIdx.x;
    const int idx = blockIdx.x * 256 + tid;
    const int ox4  = idx & 31;                // group of 4 output columns
    const int orow = idx >> 5;                // nc*128 + oy
    const int oy   = orow & 127;
    const int nc   = orow >> 7;

    const int c = ((blockIdx.x * 8) >> 7) % 3;   // 8 orows/CTA, one image/CTA
    if (tid < 7)
        sw[tid] = w[c * 169 + 78 + tid] / sqrtf(w[c * 169 + 84]);
    __syncthreads();

    float g[7];
#pragma unroll
    for (int k = 0; k < 7; k++) g[k] = sw[k];

    // tmp image rows: 128 halves = 32 uint2 per row
    const uint2* base = reinterpret_cast<const uint2*>(g_tmp + (size_t)nc * (IW * OW)) + ox4;
    const int ib = 4 * oy - 6;

    float4 acc0 = make_float4(0.f, 0.f, 0.f, 0.f);
    float4 acc1 = make_float4(0.f, 0.f, 0.f, 0.f);
#pragma unroll
    for (int k = 0; k < 13; k++) {
        const int iy = ib + k;
        const float gk = g[k < 7 ? k : 12 - k];
        if (iy >= 0 && iy < IW) {
            uint2 raw = base[(size_t)iy * 32];
            float2 f01 = __half22float2(*reinterpret_cast<__half2*>(&raw.x));
            float2 f23 = __half22float2(*reinterpret_cast<__half2*>(&raw.y));
            if (k & 1) {
                acc1.x = fmaf(gk, f01.x, acc1.x);
                acc1.y = fmaf(gk, f01.y, acc1.y);
                acc1.z = fmaf(gk, f23.x, acc1.z);
                acc1.w = fmaf(gk, f23.y, acc1.w);
            } else {
                acc0.x = fmaf(gk, f01.x, acc0.x);
                acc0.y = fmaf(gk, f01.y, acc0.y);
                acc0.z = fmaf(gk, f23.x, acc0.z);
                acc0.w = fmaf(gk, f23.y, acc0.w);
            }
        }
    }
    float4 r;
    r.x = acc0.x + acc1.x; r.y = acc0.y + acc1.y;
    r.z = acc0.z + acc1.z; r.w = acc0.w + acc1.w;
    reinterpret_cast<float4*>(out)[(size_t)orow * 32 + ox4] = r;
}

extern "C" void kernel_launch(void* const* d_in, const int* in_sizes, int n_in,
                              void* d_out, int out_size)
{
    const float* inp = (const float*)d_in[0];   // [32,3,512,512]
    const float* wgt = (const float*)d_in[1];   // [3,1,13,13]
    float* out = (float*)d_out;                 // [32,3,128,128]

    hpass_kernel<<<96 * 512 / 8, 256>>>(inp, wgt);        // 6144 CTAs
    vpass_kernel<<<96 * 128 * 32 / 256, 256>>>(wgt, out); // 1536 CTAs
}

// round 10
// speedup vs baseline: 1.0046x; 1.0046x over previous
#include <cuda_runtime.h>
#include <cuda_fp16.h>

// AntiAliasInterpolation2d: depthwise 13x13 Gaussian, stride 4, zero pad 6.
// Input [32,3,512,512] f32, weight [3,1,13,13] f32, output [32,3,128,128] f32.
//
// Separable (exact): 2D kernel = outer(g,g), g[j] = k2[6][j]/sqrt(k2[6][6]).
// R10: hpass = smem ROW STAGING: coalesced bulk load of 8 rows (pure MLP,
// no load->FMA chains), then filter from smem with a 6-float pad so every
// 13-tap window is 3 aligned LDS.128 + 1 LDS.32, conflict-free.
// vpass unchanged (fp16 intermediate, 13 independent 8B loads/thread).

#define IW   512
#define IW4  128                 // input row in float4
#define OW   128
#define SPAD 528                 // padded smem row: 6 zeros + 512 + 10 zeros

__device__ __half g_tmp[96 * 512 * 128];   // 12.6 MB scratch

// K1: CTA = 8 input rows; warp = one row. Stage to smem, then filter.
__global__ __launch_bounds__(256, 7)
void hpass_kernel(const float* __restrict__ inp, const float* __restrict__ w)
{
    __shared__ float sw[8];
    __shared__ float srow[8][SPAD];           // 16896 B

    const int tid  = threadIdx.x;
    const int lane = tid & 31;
    const int wid  = tid >> 5;

    const int row0 = blockIdx.x * 8;          // 8 | 512 -> CTA within one image
    const int c    = (row0 >> 9) % 3;
    if (tid < 7)
        sw[tid] = w[c * 169 + 78 + tid] / sqrtf(w[c * 169 + 84]);

    const int row = row0 + wid;               // nc*512 + iy
    const float4* r4 = reinterpret_cast<const float4*>(inp) + (size_t)row * IW4;

    // ---- stage: 4 coalesced LDG.128 per lane, no consumer until barrier ----
    float4 v0 = r4[lane];
    float4 v1 = r4[lane + 32];
    float4 v2 = r4[lane + 64];
    float4 v3 = r4[lane + 96];

    // zero pads
    if (lane < 6)       srow[wid][lane] = 0.f;
    else if (lane < 16) srow[wid][512 + lane] = 0.f;

    // store at +6 floats (8B-aligned) as float2 pairs
    {
        float* s = &srow[wid][6];
        float4 vv[4] = {v0, v1, v2, v3};
#pragma unroll
        for (int j = 0; j < 4; j++) {
            float* p = s + 4 * (lane + 32 * j);
            *reinterpret_cast<float2*>(p)     = make_float2(vv[j].x, vv[j].y);
            *reinterpret_cast<float2*>(p + 2) = make_float2(vv[j].z, vv[j].w);
        }
    }
    __syncthreads();

    float g[7];
#pragma unroll
    for (int k = 0; k < 7; k++) g[k] = sw[k];

    // ---- filter from smem: taps for ox start at srow[wid][4*ox] (16B aligned) ----
    __half* dst = g_tmp + (size_t)row * OW;
#pragma unroll
    for (int j = 0; j < 4; j++) {
        const int ox = lane + 32 * j;
        const float* base = &srow[wid][4 * ox];
        float4 q0 = *reinterpret_cast<const float4*>(base);      // f0..f3
        float4 q1 = *reinterpret_cast<const float4*>(base + 4);  // f4..f7
        float4 q2 = *reinterpret_cast<const float4*>(base + 8);  // f8..f11
        float  s  = base[12];                                    // f12

        float e0 =       g[0] * q0.x;      // f0
        float e1 =       g[1] * q0.y;      // f1
        e0 = fmaf(g[2], q0.z, e0);         // f2
        e1 = fmaf(g[3], q0.w, e1);         // f3
        e0 = fmaf(g[4], q1.x, e0);         // f4
        e1 = fmaf(g[5], q1.y, e1);         // f5
        e0 = fmaf(g[6], q1.z, e0);         // f6
        e1 = fmaf(g[5], q1.w, e1);         // f7
        e0 = fmaf(g[4], q2.x, e0);         // f8
        e1 = fmaf(g[3], q2.y, e1);         // f9
        e0 = fmaf(g[2], q2.z, e0);         // f10
        e1 = fmaf(g[1], q2.w, e1);         // f11
        e0 = fmaf(g[0], s,    e0);         // f12
        dst[ox] = __float2half_rn(e0 + e1);
    }
}

// K2: thread = one output float4 (393216 of them), 8 output rows per CTA.
__global__ __launch_bounds__(256, 6)
void vpass_kernel(const float* __restrict__ w, float* __restrict__ out)
{
    __shared__ float sw[8];
    const int tid = threadIdx.x;
    const int idx = blockIdx.x * 256 + tid;
    const int ox4  = idx & 31;                // group of 4 output columns
    const int orow = idx >> 5;                // nc*128 + oy
    const int oy   = orow & 127;
    const int nc   = orow >> 7;

    const int c = ((blockIdx.x * 8) >> 7) % 3;   // 8 orows/CTA, one image/CTA
    if (tid < 7)
        sw[tid] = w[c * 169 + 78 + tid] / sqrtf(w[c * 169 + 84]);
    __syncthreads();

    float g[7];
#pragma unroll
    for (int k = 0; k < 7; k++) g[k] = sw[k];

    const uint2* base = reinterpret_cast<const uint2*>(g_tmp + (size_t)nc * (IW * OW)) + ox4;
    const int ib = 4 * oy - 6;

    float4 acc0 = make_float4(0.f, 0.f, 0.f, 0.f);
    float4 acc1 = make_float4(0.f, 0.f, 0.f, 0.f);
#pragma unroll
    for (int k = 0; k < 13; k++) {
        const int iy = ib + k;
        const float gk = g[k < 7 ? k : 12 - k];
        if (iy >= 0 && iy < IW) {
            uint2 raw = base[(size_t)iy * 32];
            float2 f01 = __half22float2(*reinterpret_cast<__half2*>(&raw.x));
            float2 f23 = __half22float2(*reinterpret_cast<__half2*>(&raw.y));
            if (k & 1) {
                acc1.x = fmaf(gk, f01.x, acc1.x);
                acc1.y = fmaf(gk, f01.y, acc1.y);
                acc1.z = fmaf(gk, f23.x, acc1.z);
                acc1.w = fmaf(gk, f23.y, acc1.w);
            } else {
                acc0.x = fmaf(gk, f01.x, acc0.x);
                acc0.y = fmaf(gk, f01.y, acc0.y);
                acc0.z = fmaf(gk, f23.x, acc0.z);
                acc0.w = fmaf(gk, f23.y, acc0.w);
            }
        }
    }
    float4 r;
    r.x = acc0.x + acc1.x; r.y = acc0.y + acc1.y;
    r.z = acc0.z + acc1.z; r.w = acc0.w + acc1.w;
    reinterpret_cast<float4*>(out)[(size_t)orow * 32 + ox4] = r;
}

extern "C" void kernel_launch(void* const* d_in, const int* in_sizes, int n_in,
                              void* d_out, int out_size)
{
    const float* inp = (const float*)d_in[0];   // [32,3,512,512]
    const float* wgt = (const float*)d_in[1];   // [3,1,13,13]
    float* out = (float*)d_out;                 // [32,3,128,128]

    hpass_kernel<<<96 * 512 / 8, 256>>>(inp, wgt);        // 6144 CTAs
    vpass_kernel<<<96 * 128 * 32 / 256, 256>>>(wgt, out); // 1536 CTAs
}

// round 11
// speedup vs baseline: 1.1301x; 1.1250x over previous
#include <cuda_runtime.h>
#include <cuda_fp16.h>

// AntiAliasInterpolation2d: depthwise 13x13 Gaussian, stride 4, zero pad 6.
// Input [32,3,512,512] f32, weight [3,1,13,13] f32, output [32,3,128,128] f32.
//
// Separable (exact): 2D kernel = outer(g,g), g[j] = k2[6][j]/sqrt(k2[6][6]).
// R11: hpass = 2 rows per warp with ALL 8 float4 loads in flight before the
// FMAs (fixes the per-warp work-quantum serialization that kept every prior
// hpass at ~26us), input loaded with __ldcs (evict-first) so the 12.6 MB fp16
// intermediate stays L2-resident for vpass. No smem, no barriers in hpass.

#define IW   512
#define IW4  128                 // input row in float4
#define OW   128

__device__ __half g_tmp[96 * 512 * 128];   // 12.6 MB scratch (L2-resident)

__device__ __forceinline__ float4 ldcs4(const float4* p) { return __ldcs(p); }

// K1: warp = TWO adjacent input rows; CTA = 16 rows; 3072 CTAs.
__global__ __launch_bounds__(256, 4)
void hpass_kernel(const float* __restrict__ inp, const float* __restrict__ w)
{
    const int tid  = threadIdx.x;
    const int lane = tid & 31;
    const int wid  = tid >> 5;

    const int wg = blockIdx.x * 8 + wid;      // global warp id
    const int r0 = 2 * wg;                    // rows r0, r0+1 (same image: 2|512)
    const int c  = (r0 >> 9) % 3;

    // per-thread weights (warp-uniform addresses -> single wavefront each)
    float g[7];
    {
        const float inv = 1.0f / sqrtf(w[c * 169 + 84]);
#pragma unroll
        for (int k = 0; k < 7; k++) g[k] = w[c * 169 + 78 + k] * inv;
    }

    const float4* ra = reinterpret_cast<const float4*>(inp) + (size_t)r0 * IW4;
    const float4* rb = ra + IW4;
    __half* da = g_tmp + (size_t)r0 * OW;
    __half* db = da + OW;

    const float4 z4 = make_float4(0.f, 0.f, 0.f, 0.f);

#pragma unroll
    for (int j = 0; j < 4; j++) {
        const int ox = lane + 32 * j;
        // 8 independent evict-first loads, all issued before any FMA
        float4 a0 = (ox >= 2)       ? ldcs4(ra + ox - 2) : z4;
        float4 a1 = (ox >= 1)       ? ldcs4(ra + ox - 1) : z4;
        float4 a2 =                   ldcs4(ra + ox);
        float4 a3 = (ox <= IW4 - 2) ? ldcs4(ra + ox + 1) : z4;
        float4 b0 = (ox >= 2)       ? ldcs4(rb + ox - 2) : z4;
        float4 b1 = (ox >= 1)       ? ldcs4(rb + ox - 1) : z4;
        float4 b2 =                   ldcs4(rb + ox);
        float4 b3 = (ox <= IW4 - 2) ? ldcs4(rb + ox + 1) : z4;

        // taps k=0..12 at components z,w | xyzw | xyzw | x,y,z ; g[k]==g[12-k]
        float e0 =       g[0] * a0.z;
        float e1 =       g[1] * a0.w;
        e0 = fmaf(g[2], a1.x, e0);
        e1 = fmaf(g[3], a1.y, e1);
        e0 = fmaf(g[4], a1.z, e0);
        e1 = fmaf(g[5], a1.w, e1);
        e0 = fmaf(g[6], a2.x, e0);
        e1 = fmaf(g[5], a2.y, e1);
        e0 = fmaf(g[4], a2.z, e0);
        e1 = fmaf(g[3], a2.w, e1);
        e0 = fmaf(g[2], a3.x, e0);
        e1 = fmaf(g[1], a3.y, e1);
        e0 = fmaf(g[0], a3.z, e0);

        float f0 =       g[0] * b0.z;
        float f1 =       g[1] * b0.w;
        f0 = fmaf(g[2], b1.x, f0);
        f1 = fmaf(g[3], b1.y, f1);
        f0 = fmaf(g[4], b1.z, f0);
        f1 = fmaf(g[5], b1.w, f1);
        f0 = fmaf(g[6], b2.x, f0);
        f1 = fmaf(g[5], b2.y, f1);
        f0 = fmaf(g[4], b2.z, f0);
        f1 = fmaf(g[3], b2.w, f1);
        f0 = fmaf(g[2], b3.x, f0);
        f1 = fmaf(g[1], b3.y, f1);
        f0 = fmaf(g[0], b3.z, f0);

        da[ox] = __float2half_rn(e0 + e1);
        db[ox] = __float2half_rn(f0 + f1);
    }
}

// K2: thread = one output float4 (393216), 8 output rows per CTA.
__global__ __launch_bounds__(256, 6)
void vpass_kernel(const float* __restrict__ w, float* __restrict__ out)
{
    __shared__ float sw[8];
    const int tid = threadIdx.x;
    const int idx = blockIdx.x * 256 + tid;
    const int ox4  = idx & 31;                // group of 4 output columns
    const int orow = idx >> 5;                // nc*128 + oy
    const int oy   = orow & 127;
    const int nc   = orow >> 7;

    const int c = ((blockIdx.x * 8) >> 7) % 3;   // 8 orows/CTA, one image/CTA
    if (tid < 7)
        sw[tid] = w[c * 169 + 78 + tid] / sqrtf(w[c * 169 + 84]);
    __syncthreads();

    float g[7];
#pragma unroll
    for (int k = 0; k < 7; k++) g[k] = sw[k];

    const uint2* base = reinterpret_cast<const uint2*>(g_tmp + (size_t)nc * (IW * OW)) + ox4;
    const int ib = 4 * oy - 6;

    float4 acc0 = make_float4(0.f, 0.f, 0.f, 0.f);
    float4 acc1 = make_float4(0.f, 0.f, 0.f, 0.f);
#pragma unroll
    for (int k = 0; k < 13; k++) {
        const int iy = ib + k;
        const float gk = g[k < 7 ? k : 12 - k];
        if (iy >= 0 && iy < IW) {
            uint2 raw = base[(size_t)iy * 32];
            float2 f01 = __half22float2(*reinterpret_cast<__half2*>(&raw.x));
            float2 f23 = __half22float2(*reinterpret_cast<__half2*>(&raw.y));
            if (k & 1) {
                acc1.x = fmaf(gk, f01.x, acc1.x);
                acc1.y = fmaf(gk, f01.y, acc1.y);
                acc1.z = fmaf(gk, f23.x, acc1.z);
                acc1.w = fmaf(gk, f23.y, acc1.w);
            } else {
                acc0.x = fmaf(gk, f01.x, acc0.x);
                acc0.y = fmaf(gk, f01.y, acc0.y);
                acc0.z = fmaf(gk, f23.x, acc0.z);
                acc0.w = fmaf(gk, f23.y, acc0.w);
            }
        }
    }
    float4 r;
    r.x = acc0.x + acc1.x; r.y = acc0.y + acc1.y;
    r.z = acc0.z + acc1.z; r.w = acc0.w + acc1.w;
    reinterpret_cast<float4*>(out)[(size_t)orow * 32 + ox4] = r;
}

extern "C" void kernel_launch(void* const* d_in, const int* in_sizes, int n_in,
                              void* d_out, int out_size)
{
    const float* inp = (const float*)d_in[0];   // [32,3,512,512]
    const float* wgt = (const float*)d_in[1];   // [3,1,13,13]
    float* out = (float*)d_out;                 // [32,3,128,128]

    hpass_kernel<<<96 * 512 / 16, 256>>>(inp, wgt);       // 3072 CTAs
    vpass_kernel<<<96 * 128 * 32 / 256, 256>>>(wgt, out); // 1536 CTAs
}

// round 12
// speedup vs baseline: 1.1989x; 1.0609x over previous
#include <cuda_runtime.h>
#include <cuda_fp16.h>

// AntiAliasInterpolation2d: depthwise 13x13 Gaussian, stride 4, zero pad 6.
// Input [32,3,512,512] f32, weight [3,1,13,13] f32, output [32,3,128,128] f32.
//
// Separable (exact): 2D kernel = outer(g,g), g[j] = k2[6][j]/sqrt(k2[6][6]).
// R12: hpass at 6 CTAs/SM (12 warps/SMSP x 46 issue-cyc covers the 577-cyc
// DRAM stall -> ~96% latency hiding per the R11-validated duty-cycle model).
// vpass: one thread computes an oy-PAIR (windows share 9 rows): 17 loads
// instead of 26 for the same FMA count (vpass is issue-bound at 47%).

#define IW   512
#define IW4  128                 // input row in float4
#define OW   128

__device__ __half g_tmp[96 * 512 * 128];   // 12.6 MB scratch

__device__ __forceinline__ float4 ldcs4(const float4* p) { return __ldcs(p); }

// K1: warp = TWO adjacent input rows; CTA = 16 rows; 3072 CTAs.
__global__ __launch_bounds__(256, 6)
void hpass_kernel(const float* __restrict__ inp, const float* __restrict__ w)
{
    const int tid  = threadIdx.x;
    const int lane = tid & 31;
    const int wid  = tid >> 5;

    const int wg = blockIdx.x * 8 + wid;      // global warp id
    const int r0 = 2 * wg;                    // rows r0, r0+1 (same image: 2|512)
    const int c  = (r0 >> 9) % 3;

    float g[7];
    {
        const float inv = 1.0f / sqrtf(w[c * 169 + 84]);
#pragma unroll
        for (int k = 0; k < 7; k++) g[k] = w[c * 169 + 78 + k] * inv;
    }

    const float4* ra = reinterpret_cast<const float4*>(inp) + (size_t)r0 * IW4;
    const float4* rb = ra + IW4;
    __half* da = g_tmp + (size_t)r0 * OW;

    const float4 z4 = make_float4(0.f, 0.f, 0.f, 0.f);

#pragma unroll
    for (int j = 0; j < 4; j++) {
        const int ox = lane + 32 * j;
        // 8 independent evict-first loads, all issued before any FMA
        float4 a0 = (ox >= 2)       ? ldcs4(ra + ox - 2) : z4;
        float4 a1 = (ox >= 1)       ? ldcs4(ra + ox - 1) : z4;
        float4 a2 =                   ldcs4(ra + ox);
        float4 a3 = (ox <= IW4 - 2) ? ldcs4(ra + ox + 1) : z4;
        float4 b0 = (ox >= 2)       ? ldcs4(rb + ox - 2) : z4;
        float4 b1 = (ox >= 1)       ? ldcs4(rb + ox - 1) : z4;
        float4 b2 =                   ldcs4(rb + ox);
        float4 b3 = (ox <= IW4 - 2) ? ldcs4(rb + ox + 1) : z4;

        float e0 =       g[0] * a0.z;
        float e1 =       g[1] * a0.w;
        e0 = fmaf(g[2], a1.x, e0);
        e1 = fmaf(g[3], a1.y, e1);
        e0 = fmaf(g[4], a1.z, e0);
        e1 = fmaf(g[5], a1.w, e1);
        e0 = fmaf(g[6], a2.x, e0);
        e1 = fmaf(g[5], a2.y, e1);
        e0 = fmaf(g[4], a2.z, e0);
        e1 = fmaf(g[3], a2.w, e1);
        e0 = fmaf(g[2], a3.x, e0);
        e1 = fmaf(g[1], a3.y, e1);
        e0 = fmaf(g[0], a3.z, e0);

        float f0 =       g[0] * b0.z;
        float f1 =       g[1] * b0.w;
        f0 = fmaf(g[2], b1.x, f0);
        f1 = fmaf(g[3], b1.y, f1);
        f0 = fmaf(g[4], b1.z, f0);
        f1 = fmaf(g[5], b1.w, f1);
        f0 = fmaf(g[6], b2.x, f0);
        f1 = fmaf(g[5], b2.y, f1);
        f0 = fmaf(g[4], b2.z, f0);
        f1 = fmaf(g[3], b2.w, f1);
        f0 = fmaf(g[2], b3.x, f0);
        f1 = fmaf(g[1], b3.y, f1);
        f0 = fmaf(g[0], b3.z, f0);

        da[ox]      = __float2half_rn(e0 + e1);
        da[OW + ox] = __float2half_rn(f0 + f1);
    }
}

// K2: thread = one float4 column-group of an oy-PAIR. Warp = one row-pair.
// 96 images * 64 pairs * 32 col-groups = 196608 threads -> 768 CTAs.
__global__ __launch_bounds__(256, 6)
void vpass_kernel(const float* __restrict__ w, float* __restrict__ out)
{
    __shared__ float sw[8];
    const int tid = threadIdx.x;
    const int idx = blockIdx.x * 256 + tid;
    const int ox4 = idx & 31;                 // float4 column group
    const int t   = idx >> 5;                 // pair id: nc*64 + oyp
    const int oyp = t & 63;
    const int nc  = t >> 6;
    const int oy0 = 2 * oyp;

    const int c = ((blockIdx.x * 8) >> 6) % 3;   // 8 pairs/CTA, 8|64 -> one image
    if (tid < 7)
        sw[tid] = w[c * 169 + 78 + tid] / sqrtf(w[c * 169 + 84]);
    __syncthreads();

    float g[7];
#pragma unroll
    for (int k = 0; k < 7; k++) g[k] = sw[k];

    const uint2* base = reinterpret_cast<const uint2*>(g_tmp + (size_t)nc * (IW * OW)) + ox4;
    const int ib = 4 * oy0 - 6;               // first row of out0's window

    // out0 uses k=0..12 (g[sym k]); out1 uses k=4..16 (g[sym (k-4)])
    float4 p0 = make_float4(0.f, 0.f, 0.f, 0.f);
    float4 p1 = make_float4(0.f, 0.f, 0.f, 0.f);
#pragma unroll
    for (int k = 0; k < 17; k++) {
        const int iy = ib + k;
        if (iy >= 0 && iy < IW) {
            uint2 raw = base[(size_t)iy * 32];
            float2 f01 = __half22float2(*reinterpret_cast<__half2*>(&raw.x));
            float2 f23 = __half22float2(*reinterpret_cast<__half2*>(&raw.y));
            if (k <= 12) {
                const float gk = g[k < 7 ? k : 12 - k];
                p0.x = fmaf(gk, f01.x, p0.x);
                p0.y = fmaf(gk, f01.y, p0.y);
                p0.z = fmaf(gk, f23.x, p0.z);
                p0.w = fmaf(gk, f23.y, p0.w);
            }
            if (k >= 4) {
                const int m = k - 4;
                const float gm = g[m < 7 ? m : 12 - m];
                p1.x = fmaf(gm, f01.x, p1.x);
                p1.y = fmaf(gm, f01.y, p1.y);
                p1.z = fmaf(gm, f23.x, p1.z);
                p1.w = fmaf(gm, f23.y, p1.w);
            }
        }
    }
    float4* ob = reinterpret_cast<float4*>(out) + ((size_t)nc * 128 + oy0) * 32 + ox4;
    ob[0]  = p0;
    ob[32] = p1;
}

extern "C" void kernel_launch(void* const* d_in, const int* in_sizes, int n_in,
                              void* d_out, int out_size)
{
    const float* inp = (const float*)d_in[0];   // [32,3,512,512]
    const float* wgt = (const float*)d_in[1];   // [3,1,13,13]
    float* out = (float*)d_out;                 // [32,3,128,128]

    hpass_kernel<<<96 * 512 / 16, 256>>>(inp, wgt);       // 3072 CTAs
    vpass_kernel<<<96 * 64 * 32 / 256, 256>>>(wgt, out);  // 768 CTAs
}